// round 2
// baseline (speedup 1.0000x reference)
#include <cuda_runtime.h>
#include <cstdint>

#define B_   128
#define T_   64
#define V_   1024
#define TS_  64
#define H_   512
#define NTOK (B_ * T_)      // 8192
#define G3   (3 * H_)       // 1536
#define IN_  (V_ + TS_)     // 1088

// ---------------- device scratch (static allocation only) ----------------
__device__ float g_xg[NTOK * G3];     // [8192, 1536] gate pre-activations
__device__ float g_coefA[G3];
__device__ float g_coefC[G3];

// ---------------- kernel 0: fold time-embedding into per-gate coefficients ----------------
// t_emb contribution to xg[n,g] = interval[n]*A[g] + C[g]
__global__ void coef_kernel(const float* __restrict__ W_time,
                            const float* __restrict__ b_time,
                            const float* __restrict__ W_ih,
                            const float* __restrict__ b_ih)
{
    int g = blockIdx.x * blockDim.x + threadIdx.x;
    if (g >= G3) return;
    const float* wrow = W_ih + (size_t)g * IN_ + V_;
    float a = 0.f, cc = 0.f;
#pragma unroll 8
    for (int j = 0; j < TS_; j++) {
        float wv = wrow[j];
        a  += W_time[j] * wv;
        cc += b_time[j] * wv;
    }
    g_coefA[g] = a;
    g_coefC[g] = cc + b_ih[g];
}

// ---------------- kernel 1: xg = visit_emb @ W_ih[:, :V]^T  (+ epilogue) ----------------
// M=8192 (tokens), N=1536 (gates), K=1024. Both operands K-contiguous (NT GEMM).
#define BM 128
#define BN 128
#define BK 16
#define AST 132   // padded smem stride to break transpose-store bank conflicts

__global__ __launch_bounds__(256, 2)
void gemm_kernel(const float* __restrict__ A,        // visit_emb [8192,1024]
                 const float* __restrict__ Bw,       // W_ih [1536,1088]
                 const float* __restrict__ interval) // [8192]
{
    __shared__ float As[BK][AST];
    __shared__ float Bs[BK][AST];

    int tid = threadIdx.x;
    int tx = tid & 15;          // 0..15 -> N micro
    int ty = tid >> 4;          // 0..15 -> M micro
    int rowBase = blockIdx.y * BM;
    int colBase = blockIdx.x * BN;

    int lr = tid >> 2;          // 0..63
    int kq = tid & 3;           // 0..3 (float4 group within BK)

    float acc[8][8];
#pragma unroll
    for (int i = 0; i < 8; i++)
#pragma unroll
        for (int j = 0; j < 8; j++) acc[i][j] = 0.f;

    const float* Aptr = A  + (size_t)(rowBase + lr) * V_  + kq * 4;
    const float* Bptr = Bw + (size_t)(colBase + lr) * IN_ + kq * 4;

    for (int kt = 0; kt < V_; kt += BK) {
        float4 a0 = *(const float4*)(Aptr + kt);
        float4 a1 = *(const float4*)(Aptr + (size_t)64 * V_ + kt);
        float4 b0 = *(const float4*)(Bptr + kt);
        float4 b1 = *(const float4*)(Bptr + (size_t)64 * IN_ + kt);

        __syncthreads();
        As[kq*4+0][lr] = a0.x; As[kq*4+1][lr] = a0.y; As[kq*4+2][lr] = a0.z; As[kq*4+3][lr] = a0.w;
        As[kq*4+0][lr+64] = a1.x; As[kq*4+1][lr+64] = a1.y; As[kq*4+2][lr+64] = a1.z; As[kq*4+3][lr+64] = a1.w;
        Bs[kq*4+0][lr] = b0.x; Bs[kq*4+1][lr] = b0.y; Bs[kq*4+2][lr] = b0.z; Bs[kq*4+3][lr] = b0.w;
        Bs[kq*4+0][lr+64] = b1.x; Bs[kq*4+1][lr+64] = b1.y; Bs[kq*4+2][lr+64] = b1.z; Bs[kq*4+3][lr+64] = b1.w;
        __syncthreads();

#pragma unroll
        for (int kk = 0; kk < BK; kk++) {
            float av[8], bv[8];
            *(float4*)(av+0) = *(const float4*)&As[kk][ty*8];
            *(float4*)(av+4) = *(const float4*)&As[kk][ty*8+4];
            *(float4*)(bv+0) = *(const float4*)&Bs[kk][tx*8];
            *(float4*)(bv+4) = *(const float4*)&Bs[kk][tx*8+4];
#pragma unroll
            for (int i = 0; i < 8; i++)
#pragma unroll
                for (int j = 0; j < 8; j++)
                    acc[i][j] += av[i] * bv[j];
        }
    }

    // epilogue: + interval[n]*A[g] + C[g]
    float ai[8], ca[8], cc[8];
#pragma unroll
    for (int i = 0; i < 8; i++) ai[i] = interval[rowBase + ty*8 + i];
#pragma unroll
    for (int j = 0; j < 8; j++) {
        ca[j] = g_coefA[colBase + tx*8 + j];
        cc[j] = g_coefC[colBase + tx*8 + j];
    }
#pragma unroll
    for (int i = 0; i < 8; i++) {
        size_t rbase = (size_t)(rowBase + ty*8 + i) * G3 + colBase + tx*8;
#pragma unroll
        for (int j = 0; j < 8; j++)
            g_xg[rbase + j] = acc[i][j] + ai[i] * ca[j] + cc[j];
    }
}

// ---------------- kernel 2: persistent cluster GRU scan ----------------
// 16 CTAs (one cluster), 512 threads each. CTA c owns hidden slice j in [32c,32c+32)
// and W_hh rows {j, 512+j, 1024+j}. Warp w handles j0=32c+2w, j0+1 (6 rows).
// Lane l covers columns [16l,16l+16). Per step: smem matvec -> butterfly reduce ->
// gate math on lanes 0,1 -> DSMEM broadcast of 32 new h values -> cluster.sync.
// Masked steps (t >= lens[b]) are skipped entirely.

#define SCAN_W_FLOATS (96 * 512)              // 49152
#define SCAN_SMEM_FLOATS (SCAN_W_FLOATS + 1024 + 32 + 128)
#define SCAN_SMEM_BYTES (SCAN_SMEM_FLOATS * 4) // 201344

__global__ void __launch_bounds__(512, 1)
scan_kernel(const float* __restrict__ W_hh,
            const float* __restrict__ b_hh,
            const int*   __restrict__ lens,
            float*       __restrict__ out)
{
    extern __shared__ float sm[];
    float* Wsm   = sm;                         // 49152 floats
    float* hb    = sm + SCAN_W_FLOATS;         // 2 x 512 (parity buffers)
    float* stage = hb + 1024;                  // 32
    int*   lens_sm = (int*)(stage + 32);       // 128

    int tid = threadIdx.x;
    int w = tid >> 5;
    int l = tid & 31;
    uint32_t c;
    asm("mov.u32 %0, %%cluster_ctarank;" : "=r"(c));

    // load W_hh slice into smem with per-row layout:
    //   Wsm[slot*512 + q*128 + l*4 + e] = W[row][l*16 + q*4 + e]
    // so each lane's 4 LDS.128 per row are bank-conflict free.
    for (int idx = tid; idx < SCAN_W_FLOATS; idx += 512) {
        int slot = idx >> 9;
        int col  = idx & 511;
        int ww = slot / 6;
        int s  = slot - ww * 6;
        int j0 = 32 * (int)c + 2 * ww;
        int row = (s < 2) ? (j0 + s) : (s < 4) ? (H_ + j0 + s - 2) : (2 * H_ + j0 + s - 4);
        int lq = col >> 4;
        int qq = (col >> 2) & 3;
        int e  = col & 3;
        Wsm[slot * 512 + qq * 128 + lq * 4 + e] = W_hh[(size_t)row * H_ + col];
    }
    if (tid < 128) lens_sm[tid] = lens[tid];
    hb[tid] = 0.f;
    hb[512 + tid] = 0.f;
    __syncthreads();
    asm volatile("barrier.cluster.arrive.aligned;" ::: "memory");
    asm volatile("barrier.cluster.wait.aligned;"   ::: "memory");

    bool gate = (l < 2);
    int jg = 32 * (int)c + 2 * w + l;   // valid only for gate lanes
    float br = 0.f, bz = 0.f, bn = 0.f;
    if (gate) { br = b_hh[jg]; bz = b_hh[H_ + jg]; bn = b_hh[2 * H_ + jg]; }
    uint32_t hb_s = (uint32_t)__cvta_generic_to_shared(hb);

    int p = 0;
    for (int b = 0; b < B_; b++) {
        int len = lens_sm[b];
        for (int t = 0; t < len; t++) {
            int n = b * T_ + t;

            // issue gate-input loads early; hidden under the matvec
            float xr = 0.f, xz = 0.f, xn = 0.f;
            if (gate) {
                const float* xp = g_xg + (size_t)n * G3 + jg;
                xr = xp[0];
                xz = xp[H_];
                xn = xp[2 * H_];
            }

            const float* hp = hb + p * 512;
            float hq[16];
#pragma unroll
            for (int q = 0; q < 4; q++) {
                float4 hv = *(const float4*)(hp + l * 16 + q * 4);
                hq[4*q+0] = hv.x; hq[4*q+1] = hv.y; hq[4*q+2] = hv.z; hq[4*q+3] = hv.w;
            }

            float acc[6];
            const float* wp = Wsm + (w * 6) * 512 + l * 4;
#pragma unroll
            for (int s = 0; s < 6; s++) {
                const float* wr = wp + s * 512;
                float a = 0.f;
#pragma unroll
                for (int q = 0; q < 4; q++) {
                    float4 wv = *(const float4*)(wr + q * 128);
                    a += wv.x * hq[4*q+0] + wv.y * hq[4*q+1]
                       + wv.z * hq[4*q+2] + wv.w * hq[4*q+3];
                }
                acc[s] = a;
            }

#pragma unroll
            for (int off = 16; off > 0; off >>= 1) {
#pragma unroll
                for (int s = 0; s < 6; s++)
                    acc[s] += __shfl_xor_sync(0xffffffffu, acc[s], off);
            }

            if (gate) {
                float hold = hb[p * 512 + jg];
                float rr = 1.f / (1.f + expf(-(xr + acc[l]     + br)));
                float zz = 1.f / (1.f + expf(-(xz + acc[2 + l] + bz)));
                float nn = tanhf(xn + rr * (acc[4 + l] + bn));
                stage[2 * w + l] = (1.f - zz) * nn + zz * hold;
            }
            __syncthreads();

            // broadcast this CTA's 32 new h values to every cluster CTA's hb[1-p]
            {
                float v = stage[l];
                uint32_t laddr = hb_s + (uint32_t)((((p ^ 1) * 512) + 32 * (int)c + l) * 4);
                uint32_t raddr;
                asm volatile("mapa.shared::cluster.u32 %0, %1, %2;"
                             : "=r"(raddr) : "r"(laddr), "r"(w));
                asm volatile("st.shared::cluster.b32 [%0], %1;"
                             :: "r"(raddr), "r"(__float_as_uint(v)) : "memory");
            }

            asm volatile("barrier.cluster.arrive.aligned;" ::: "memory");
            asm volatile("barrier.cluster.wait.aligned;"   ::: "memory");
            p ^= 1;
        }
        // hidden state after sample b (masked tail leaves h unchanged)
        if (tid < 32)
            out[b * H_ + 32 * (int)c + tid] = hb[p * 512 + 32 * (int)c + tid];
    }
}

// ---------------- launcher ----------------
extern "C" void kernel_launch(void* const* d_in, const int* in_sizes, int n_in,
                              void* d_out, int out_size)
{
    const float* visit_emb = (const float*)d_in[0];
    const float* intervals = (const float*)d_in[1];
    const float* W_time    = (const float*)d_in[2];
    const float* b_time    = (const float*)d_in[3];
    const float* W_ih      = (const float*)d_in[4];
    const float* W_hh      = (const float*)d_in[5];
    const float* b_ih      = (const float*)d_in[6];
    const float* b_hh      = (const float*)d_in[7];
    const int*   lens      = (const int*)d_in[8];
    float* out = (float*)d_out;

    coef_kernel<<<(G3 + 255) / 256, 256>>>(W_time, b_time, W_ih, b_ih);

    dim3 ggrid(G3 / BN, NTOK / BM);   // (12, 64)
    gemm_kernel<<<ggrid, 256>>>(visit_emb, W_ih, intervals);

    cudaFuncSetAttribute(scan_kernel, cudaFuncAttributeMaxDynamicSharedMemorySize, SCAN_SMEM_BYTES);
    cudaFuncSetAttribute(scan_kernel, cudaFuncAttributeNonPortableClusterSizeAllowed, 1);

    cudaLaunchConfig_t cfg = {};
    cfg.gridDim  = dim3(16, 1, 1);
    cfg.blockDim = dim3(512, 1, 1);
    cfg.dynamicSmemBytes = SCAN_SMEM_BYTES;
    cfg.stream = 0;
    cudaLaunchAttribute attrs[1];
    attrs[0].id = cudaLaunchAttributeClusterDimension;
    attrs[0].val.clusterDim.x = 16;
    attrs[0].val.clusterDim.y = 1;
    attrs[0].val.clusterDim.z = 1;
    cfg.attrs = attrs;
    cfg.numAttrs = 1;

    cudaLaunchKernelEx(&cfg, scan_kernel, W_hh, b_hh, lens, out);
}

// round 3
// speedup vs baseline: 1.3326x; 1.3326x over previous
#include <cuda_runtime.h>
#include <cstdint>

#define B_   128
#define T_   64
#define V_   1024
#define TS_  64
#define H_   512
#define NTOK (B_ * T_)      // 8192
#define G3   (3 * H_)       // 1536
#define IN_  (V_ + TS_)     // 1088

typedef unsigned long long ull;

// ---------------- packed fp32x2 helpers (Blackwell) ----------------
__device__ __forceinline__ ull ffma2(ull a, ull b, ull c) {
    ull d;
    asm("fma.rn.f32x2 %0, %1, %2, %3;" : "=l"(d) : "l"(a), "l"(b), "l"(c));
    return d;
}
__device__ __forceinline__ ull dup2(float a) {
    ull d; unsigned u = __float_as_uint(a);
    asm("mov.b64 %0, {%1, %2};" : "=l"(d) : "r"(u), "r"(u));
    return d;
}
__device__ __forceinline__ float2 u2f(ull a) {
    float2 f; unsigned lo, hi;
    asm("mov.b64 {%0, %1}, %2;" : "=r"(lo), "=r"(hi) : "l"(a));
    f.x = __uint_as_float(lo); f.y = __uint_as_float(hi);
    return f;
}

// ---------------- device scratch ----------------
__device__ float g_xg[NTOK * G3];     // [8192, 1536] gate pre-activations
__device__ float g_coefA[G3];
__device__ float g_coefC[G3];

// ---------------- kernel 0: fold time-embedding into coefficients ----------------
__global__ void coef_kernel(const float* __restrict__ W_time,
                            const float* __restrict__ b_time,
                            const float* __restrict__ W_ih,
                            const float* __restrict__ b_ih)
{
    int g = blockIdx.x * blockDim.x + threadIdx.x;
    if (g >= G3) return;
    const float* wrow = W_ih + (size_t)g * IN_ + V_;
    float a = 0.f, cc = 0.f;
#pragma unroll 8
    for (int j = 0; j < TS_; j++) {
        float wv = wrow[j];
        a  += W_time[j] * wv;
        cc += b_time[j] * wv;
    }
    g_coefA[g] = a;
    g_coefC[g] = cc + b_ih[g];
}

// ---------------- kernel 1: xg = visit_emb @ W_ih[:, :V]^T (+ epilogue) ----------------
#define BM 128
#define BN 128
#define BK 16
#define AST 132

__global__ __launch_bounds__(256, 2)
void gemm_kernel(const float* __restrict__ A,
                 const float* __restrict__ Bw,
                 const float* __restrict__ interval)
{
    __shared__ float As[BK][AST];
    __shared__ float Bs[BK][AST];

    int tid = threadIdx.x;
    int tx = tid & 15;
    int ty = tid >> 4;
    int rowBase = blockIdx.y * BM;
    int colBase = blockIdx.x * BN;

    int lr = tid >> 2;
    int kq = tid & 3;

    ull acc2[8][4];
#pragma unroll
    for (int i = 0; i < 8; i++)
#pragma unroll
        for (int j = 0; j < 4; j++) acc2[i][j] = 0ull;

    const float* Aptr = A  + (size_t)(rowBase + lr) * V_  + kq * 4;
    const float* Bptr = Bw + (size_t)(colBase + lr) * IN_ + kq * 4;

    for (int kt = 0; kt < V_; kt += BK) {
        float4 a0 = *(const float4*)(Aptr + kt);
        float4 a1 = *(const float4*)(Aptr + (size_t)64 * V_ + kt);
        float4 b0 = *(const float4*)(Bptr + kt);
        float4 b1 = *(const float4*)(Bptr + (size_t)64 * IN_ + kt);

        __syncthreads();
        As[kq*4+0][lr] = a0.x; As[kq*4+1][lr] = a0.y; As[kq*4+2][lr] = a0.z; As[kq*4+3][lr] = a0.w;
        As[kq*4+0][lr+64] = a1.x; As[kq*4+1][lr+64] = a1.y; As[kq*4+2][lr+64] = a1.z; As[kq*4+3][lr+64] = a1.w;
        Bs[kq*4+0][lr] = b0.x; Bs[kq*4+1][lr] = b0.y; Bs[kq*4+2][lr] = b0.z; Bs[kq*4+3][lr] = b0.w;
        Bs[kq*4+0][lr+64] = b1.x; Bs[kq*4+1][lr+64] = b1.y; Bs[kq*4+2][lr+64] = b1.z; Bs[kq*4+3][lr+64] = b1.w;
        __syncthreads();

#pragma unroll
        for (int kk = 0; kk < BK; kk++) {
            const float* ap = &As[kk][ty*8];
            float av[8];
            *(float4*)(av+0) = *(const float4*)(ap);
            *(float4*)(av+4) = *(const float4*)(ap + 4);
            const ull* bp = (const ull*)&Bs[kk][tx*8];
            ull bv0 = bp[0], bv1 = bp[1], bv2 = bp[2], bv3 = bp[3];
#pragma unroll
            for (int i = 0; i < 8; i++) {
                ull a2 = dup2(av[i]);
                acc2[i][0] = ffma2(a2, bv0, acc2[i][0]);
                acc2[i][1] = ffma2(a2, bv1, acc2[i][1]);
                acc2[i][2] = ffma2(a2, bv2, acc2[i][2]);
                acc2[i][3] = ffma2(a2, bv3, acc2[i][3]);
            }
        }
    }

    // epilogue: + interval[n]*A[g] + C[g]
    float ai[8], ca[8], cc[8];
#pragma unroll
    for (int i = 0; i < 8; i++) ai[i] = interval[rowBase + ty*8 + i];
#pragma unroll
    for (int j = 0; j < 8; j++) {
        ca[j] = g_coefA[colBase + tx*8 + j];
        cc[j] = g_coefC[colBase + tx*8 + j];
    }
#pragma unroll
    for (int i = 0; i < 8; i++) {
        size_t rbase = (size_t)(rowBase + ty*8 + i) * G3 + colBase + tx*8;
#pragma unroll
        for (int q = 0; q < 2; q++) {
            float2 v0 = u2f(acc2[i][2*q+0]);
            float2 v1 = u2f(acc2[i][2*q+1]);
            float4 o;
            o.x = v0.x + ai[i] * ca[4*q+0] + cc[4*q+0];
            o.y = v0.y + ai[i] * ca[4*q+1] + cc[4*q+1];
            o.z = v1.x + ai[i] * ca[4*q+2] + cc[4*q+2];
            o.w = v1.y + ai[i] * ca[4*q+3] + cc[4*q+3];
            *(float4*)&g_xg[rbase + 4*q] = o;
        }
    }
}

// ---------------- kernel 2: persistent cluster GRU scan, weights in registers ----------------
// 16-CTA cluster, 512 threads. CTA c owns hidden units [32c, 32c+32).
// Warp w owns units j0=32c+2w, j0+1 (6 W_hh rows, held in registers as f32x2).
// Lane l covers columns [16l, 16l+16). h lives in smem in a permuted layout
// (perm(col) = ((col>>2)&3)*128 + (col>>4)*4 + (col&3)) so each lane's 4
// float4 reads are bank-conflict-free. Cross-CTA h broadcast: per-warp DSMEM
// stores + mbarrier arrive (release.cluster), parity try_wait (acquire.cluster).

__device__ __forceinline__ int hperm(int col) {
    return ((col >> 2) & 3) * 128 + ((col >> 4) << 2) + (col & 3);
}

__device__ __forceinline__ void waitParityCluster(uint32_t addr, int ph) {
    asm volatile(
        "{\n\t"
        ".reg .pred p;\n\t"
        "WLOOP_%=:\n\t"
        "mbarrier.try_wait.parity.acquire.cluster.shared::cta.b64 p, [%0], %1, 0x989680;\n\t"
        "@p bra WDONE_%=;\n\t"
        "bra WLOOP_%=;\n\t"
        "WDONE_%=:\n\t"
        "}"
        :: "r"(addr), "r"(ph) : "memory");
}

__global__ void __launch_bounds__(512, 1)
scan_kernel(const float* __restrict__ W_hh,
            const float* __restrict__ b_hh,
            const int*   __restrict__ lens,
            float*       __restrict__ out)
{
    __shared__ float hb[2][512];     // permuted layout
    __shared__ float stage[32];
    __shared__ float bhh[96];        // r[0:32], z[32:64], n[64:96] for this CTA
    __shared__ int   lens_sm[128];
    __shared__ ull   mbars[2];

    int tid = threadIdx.x;
    int w = tid >> 5;
    int l = tid & 31;
    uint32_t c;
    asm("mov.u32 %0, %%cluster_ctarank;" : "=r"(c));

    hb[0][tid & 511] = 0.f;          // tid in [0,512)
    hb[1][tid] = 0.f;
    if (tid < 128) lens_sm[tid] = lens[tid];
    if (tid < 96) {
        int s = tid >> 5, u = tid & 31;
        bhh[tid] = b_hh[s * H_ + 32 * (int)c + u];
    }
    uint32_t mb_s = (uint32_t)__cvta_generic_to_shared(mbars);
    if (tid == 0) {
        asm volatile("mbarrier.init.shared.b64 [%0], 16;" :: "r"(mb_s) : "memory");
        asm volatile("mbarrier.init.shared.b64 [%0], 16;" :: "r"(mb_s + 8) : "memory");
    }
    __syncthreads();
    asm volatile("barrier.cluster.arrive.aligned;" ::: "memory");
    asm volatile("barrier.cluster.wait.aligned;"   ::: "memory");

    // ---- load this thread's 6x16 weight block into registers as f32x2 pairs ----
    int j0 = 32 * (int)c + 2 * w;
    ull W2[6][8];
    {
        const float* r0 = W_hh + (size_t)j0 * H_ + 16 * l;
#pragma unroll
        for (int s = 0; s < 6; s++) {
            int row = (s < 2) ? (j0 + s) : (s < 4) ? (H_ + j0 + s - 2) : (2 * H_ + j0 + s - 4);
            const ull* wp = (const ull*)(W_hh + (size_t)row * H_ + 16 * l);
#pragma unroll
            for (int k = 0; k < 8; k++) W2[s][k] = wp[k];
        }
        (void)r0;
    }

    // ---- precompute remote addresses (dest CTA = warp id w) ----
    uint32_t hb_s = (uint32_t)__cvta_generic_to_shared(hb);
    int jl = 32 * (int)c + l;                 // the unit this lane ships
    int pidx = hperm(jl);
    uint32_t ra_h0, ra_h1, ra_m0, ra_m1;
    {
        uint32_t la0 = hb_s + (uint32_t)(pidx * 4);
        uint32_t la1 = hb_s + (uint32_t)((512 + pidx) * 4);
        asm("mapa.shared::cluster.u32 %0, %1, %2;" : "=r"(ra_h0) : "r"(la0), "r"(w));
        asm("mapa.shared::cluster.u32 %0, %1, %2;" : "=r"(ra_h1) : "r"(la1), "r"(w));
        asm("mapa.shared::cluster.u32 %0, %1, %2;" : "=r"(ra_m0) : "r"(mb_s), "r"(w));
        asm("mapa.shared::cluster.u32 %0, %1, %2;" : "=r"(ra_m1) : "r"(mb_s + 8), "r"(w));
    }

    bool gate = (l < 2);
    int jg = j0 + l;                          // unit for gate lanes
    int jgp = hperm(jg);
    int bidx = 2 * w + l;                     // bias index within CTA slice

    int p = 0, ph0 = 0, ph1 = 0;
    bool pending = false;

    for (int b = 0; b < B_; b++) {
        int len = lens_sm[b];
        for (int t = 0; t < len; t++) {
            if (pending) {
                if (p == 0) { waitParityCluster(mb_s, ph0); ph0 ^= 1; }
                else        { waitParityCluster(mb_s + 8, ph1); ph1 ^= 1; }
                pending = false;
            }

            // gate-input loads issued early, consumed ~400 cyc later
            float xr = 0.f, xz = 0.f, xn = 0.f, br = 0.f, bz = 0.f, bn = 0.f, hold = 0.f;
            if (gate) {
                const float* xp = g_xg + (size_t)((b << 6) + t) * G3 + jg;
                xr = __ldg(xp);
                xz = __ldg(xp + H_);
                xn = __ldg(xp + 2 * H_);
                br = bhh[bidx]; bz = bhh[32 + bidx]; bn = bhh[64 + bidx];
                hold = hb[p][jgp];
            }

            // ---- matvec: 48 FFMA2 from registers ----
            const float* hp = hb[p];
            ull acc2[6] = {0ull, 0ull, 0ull, 0ull, 0ull, 0ull};
#pragma unroll
            for (int qq = 0; qq < 4; qq++) {
                const ull* hq = (const ull*)(hp + qq * 128 + l * 4);
                ull h01 = hq[0], h23 = hq[1];
#pragma unroll
                for (int s = 0; s < 6; s++) acc2[s] = ffma2(W2[s][2*qq+0], h01, acc2[s]);
#pragma unroll
                for (int s = 0; s < 6; s++) acc2[s] = ffma2(W2[s][2*qq+1], h23, acc2[s]);
            }
            float acc[6];
#pragma unroll
            for (int s = 0; s < 6; s++) { float2 f = u2f(acc2[s]); acc[s] = f.x + f.y; }

#pragma unroll
            for (int off = 16; off > 0; off >>= 1) {
#pragma unroll
                for (int s = 0; s < 6; s++)
                    acc[s] += __shfl_xor_sync(0xffffffffu, acc[s], off);
            }

            if (gate) {
                float a_r = l ? acc[1] : acc[0];
                float a_z = l ? acc[3] : acc[2];
                float a_n = l ? acc[5] : acc[4];
                float rr = __fdividef(1.f, 1.f + __expf(-(xr + a_r + br)));
                float zz = __fdividef(1.f, 1.f + __expf(-(xz + a_z + bz)));
                float ag = xn + rr * (a_n + bn);
                float nn = 1.f - __fdividef(2.f, __expf(2.f * ag) + 1.f);   // tanh
                stage[bidx] = (1.f - zz) * nn + zz * hold;
            }
            __syncthreads();

            // broadcast: warp w ships this CTA's 32 new h values to CTA w
            {
                float v = stage[l];
                uint32_t ra = p ? ra_h0 : ra_h1;     // write buffer p^1
                asm volatile("st.shared::cluster.b32 [%0], %1;"
                             :: "r"(ra), "r"(__float_as_uint(v)) : "memory");
                __syncwarp();
                if (l == 0) {
                    uint32_t rm = p ? ra_m0 : ra_m1;
                    asm volatile("mbarrier.arrive.release.cluster.shared::cluster.b64 _, [%0];"
                                 :: "r"(rm) : "memory");
                }
            }
            p ^= 1;
            pending = true;
        }

        if (pending) {
            if (p == 0) { waitParityCluster(mb_s, ph0); ph0 ^= 1; }
            else        { waitParityCluster(mb_s + 8, ph1); ph1 ^= 1; }
            pending = false;
        }
        if (tid < 32) {
            int j = 32 * (int)c + tid;
            out[b * H_ + j] = hb[p][hperm(j)];
        }
    }

    // protect smem from any in-flight remote traffic before teardown
    asm volatile("barrier.cluster.arrive.aligned;" ::: "memory");
    asm volatile("barrier.cluster.wait.aligned;"   ::: "memory");
}

// ---------------- launcher ----------------
extern "C" void kernel_launch(void* const* d_in, const int* in_sizes, int n_in,
                              void* d_out, int out_size)
{
    const float* visit_emb = (const float*)d_in[0];
    const float* intervals = (const float*)d_in[1];
    const float* W_time    = (const float*)d_in[2];
    const float* b_time    = (const float*)d_in[3];
    const float* W_ih      = (const float*)d_in[4];
    const float* W_hh      = (const float*)d_in[5];
    const float* b_ih      = (const float*)d_in[6];
    const float* b_hh      = (const float*)d_in[7];
    const int*   lens      = (const int*)d_in[8];
    float* out = (float*)d_out;

    coef_kernel<<<(G3 + 255) / 256, 256>>>(W_time, b_time, W_ih, b_ih);

    dim3 ggrid(G3 / BN, NTOK / BM);   // (12, 64)
    gemm_kernel<<<ggrid, 256>>>(visit_emb, W_ih, intervals);

    cudaFuncSetAttribute(scan_kernel, cudaFuncAttributeNonPortableClusterSizeAllowed, 1);

    cudaLaunchConfig_t cfg = {};
    cfg.gridDim  = dim3(16, 1, 1);
    cfg.blockDim = dim3(512, 1, 1);
    cfg.dynamicSmemBytes = 0;
    cfg.stream = 0;
    cudaLaunchAttribute attrs[1];
    attrs[0].id = cudaLaunchAttributeClusterDimension;
    attrs[0].val.clusterDim.x = 16;
    attrs[0].val.clusterDim.y = 1;
    attrs[0].val.clusterDim.z = 1;
    cfg.attrs = attrs;
    cfg.numAttrs = 1;

    cudaLaunchKernelEx(&cfg, scan_kernel, W_hh, b_hh, lens, out);
}